// round 6
// baseline (speedup 1.0000x reference)
#include <cuda_runtime.h>
#include <math.h>

// Problem constants
#define BB   8
#define TT   1024
#define CC   1024
#define HHD  16
#define DD   64
#define NROWS (BB*TT)      // 8192
#define FFN   (4*CC)       // 4096
#define EPS   1e-5f

// -------------------- scratch (static device memory; no allocs) ------------
__device__ float g_h  [(size_t)NROWS*CC];
__device__ float g_q  [(size_t)NROWS*CC];
__device__ float g_k  [(size_t)NROWS*CC];
__device__ float g_v  [(size_t)NROWS*CC];
__device__ float g_ctx[(size_t)NROWS*CC];
__device__ float g_x2 [(size_t)NROWS*CC];
__device__ float g_ff [(size_t)NROWS*FFN];

// ---------------------------- LayerNorm ------------------------------------
// One block per row of 1024 floats. 256 threads, one float4 each.
__global__ __launch_bounds__(256) void ln_kernel(
    const float* __restrict__ x, const float* __restrict__ w,
    const float* __restrict__ b, float* __restrict__ out)
{
    const int row = blockIdx.x;
    const int tid = threadIdx.x;
    const float4* xr = (const float4*)(x + (size_t)row * CC);
    float4 v = xr[tid];
    float s  = v.x + v.y + v.z + v.w;
    float ss = v.x*v.x + v.y*v.y + v.z*v.z + v.w*v.w;

    __shared__ float red0[8], red1[8];
    #pragma unroll
    for (int o = 16; o > 0; o >>= 1) {
        s  += __shfl_down_sync(0xffffffffu, s,  o);
        ss += __shfl_down_sync(0xffffffffu, ss, o);
    }
    const int wid = tid >> 5, lid = tid & 31;
    if (lid == 0) { red0[wid] = s; red1[wid] = ss; }
    __syncthreads();
    if (tid == 0) {
        float S = 0.f, SS = 0.f;
        #pragma unroll
        for (int i = 0; i < 8; i++) { S += red0[i]; SS += red1[i]; }
        float mu  = S * (1.f / CC);
        float var = SS * (1.f / CC) - mu * mu;
        red0[0] = mu;
        red1[0] = rsqrtf(var + EPS);
    }
    __syncthreads();
    const float mu = red0[0], rstd = red1[0];
    float4 wv = ((const float4*)w)[tid];
    float4 bv = ((const float4*)b)[tid];
    float4 o4;
    o4.x = (v.x - mu) * rstd * wv.x + bv.x;
    o4.y = (v.y - mu) * rstd * wv.y + bv.y;
    o4.z = (v.z - mu) * rstd * wv.z + bv.z;
    o4.w = (v.w - mu) * rstd * wv.w + bv.w;
    ((float4*)(out + (size_t)row * CC))[tid] = o4;
}

// ------------------------------- SGEMM -------------------------------------
// C[M,N] = epilogue(A[M,K] @ W[K,N] + bias, res)
// EPI 0: +bias         EPI 1: +bias+res        EPI 2: gelu(+bias)
// Tiles: BM=128, BN=128, BK=16, 256 threads, 8x8 per thread.
__device__ __forceinline__ float gelu_exact(float v) {
    return 0.5f * v * (1.0f + erff(v * 0.70710678118654752f));
}

template<int EPI>
__global__ __launch_bounds__(256) void sgemm_kernel(
    const float* __restrict__ A, const float* __restrict__ W,
    const float* __restrict__ bias, const float* __restrict__ res,
    float* __restrict__ C, int M, int N, int K)
{
    const int BM = 128, BN = 128, BK = 16;
    __shared__ float As[16][128];
    __shared__ float Bs[16][128];

    const int tid  = threadIdx.x;
    const int brow = blockIdx.y * BM;
    const int bcol = blockIdx.x * BN;
    const int tx = tid & 15, ty = tid >> 4;

    const int arow  = tid >> 2;   // 0..63
    const int acol4 = tid & 3;    // float4 index within BK
    const int brL   = tid >> 5;   // 0..7
    const int bc4   = tid & 31;   // float4 index within BN

    const float* Aptr = A + (size_t)brow * K;
    const float* Wptr = W + (size_t)bcol;

    float acc[8][8];
    #pragma unroll
    for (int i = 0; i < 8; i++)
        #pragma unroll
        for (int j = 0; j < 8; j++) acc[i][j] = 0.f;

    for (int kb = 0; kb < K; kb += BK) {
        // load A tile (128x16), store transposed
        #pragma unroll
        for (int r = 0; r < 2; r++) {
            int row = arow + r * 64;
            float4 t = *(const float4*)(Aptr + (size_t)row * K + kb + acol4 * 4);
            As[acol4*4 + 0][row] = t.x;
            As[acol4*4 + 1][row] = t.y;
            As[acol4*4 + 2][row] = t.z;
            As[acol4*4 + 3][row] = t.w;
        }
        // load B tile (16x128)
        #pragma unroll
        for (int r = 0; r < 2; r++) {
            int row = brL + r * 8;
            *(float4*)&Bs[row][bc4*4] =
                *(const float4*)(Wptr + (size_t)(kb + row) * N + bc4 * 4);
        }
        __syncthreads();

        #pragma unroll
        for (int k = 0; k < BK; k++) {
            float a[8], bb[8];
            *(float4*)&a[0]  = *(float4*)&As[k][ty*8];
            *(float4*)&a[4]  = *(float4*)&As[k][ty*8 + 4];
            *(float4*)&bb[0] = *(float4*)&Bs[k][tx*8];
            *(float4*)&bb[4] = *(float4*)&Bs[k][tx*8 + 4];
            #pragma unroll
            for (int i = 0; i < 8; i++)
                #pragma unroll
                for (int j = 0; j < 8; j++)
                    acc[i][j] = fmaf(a[i], bb[j], acc[i][j]);
        }
        __syncthreads();
    }

    // epilogue
    #pragma unroll
    for (int i = 0; i < 8; i++) {
        const int grow = brow + ty * 8 + i;
        #pragma unroll
        for (int j4 = 0; j4 < 2; j4++) {
            const int gcol = bcol + tx * 8 + j4 * 4;
            float4 bv = *(const float4*)(bias + gcol);
            float4 o;
            o.x = acc[i][j4*4 + 0] + bv.x;
            o.y = acc[i][j4*4 + 1] + bv.y;
            o.z = acc[i][j4*4 + 2] + bv.z;
            o.w = acc[i][j4*4 + 3] + bv.w;
            if (EPI == 1) {
                float4 r = *(const float4*)(res + (size_t)grow * N + gcol);
                o.x += r.x; o.y += r.y; o.z += r.z; o.w += r.w;
            }
            if (EPI == 2) {
                o.x = gelu_exact(o.x); o.y = gelu_exact(o.y);
                o.z = gelu_exact(o.z); o.w = gelu_exact(o.w);
            }
            *(float4*)(C + (size_t)grow * N + gcol) = o;
        }
    }
}

// --------------------------- Flash attention --------------------------------
// Causal, d=64. One block = 64 query rows of one (b, head); 64 threads, each
// thread owns one query row. q/o in registers, K/V/S tiles (32 keys) in SMEM.
__global__ __launch_bounds__(64) void flash_kernel(
    const float* __restrict__ Q, const float* __restrict__ Kg,
    const float* __restrict__ Vg, float* __restrict__ O)
{
    __shared__ float Ks[32][64];
    __shared__ float Vs[32][64];
    __shared__ float Ss[32][64];   // Ss[j][tid] layout: conflict-free

    const int qt  = blockIdx.x;          // 0..15 (q tiles of 64)
    const int bh  = blockIdx.y;          // 0..127
    const int b   = bh >> 4;
    const int hh  = bh & 15;
    const int tid = threadIdx.x;         // 0..63
    const int qrow = qt * 64 + tid;

    const size_t base = ((size_t)b * TT) * CC + (size_t)hh * DD;

    float4 q4[16], o4[16];
    {
        const float4* qp = (const float4*)(Q + base + (size_t)qrow * CC);
        #pragma unroll
        for (int i = 0; i < 16; i++) {
            q4[i] = qp[i];
            o4[i] = make_float4(0.f, 0.f, 0.f, 0.f);
        }
    }
    float m = -INFINITY, l = 0.f;

    const int nkt = 2 * qt + 2;          // k tiles of 32 covering [0, qt*64+64)
    for (int kt = 0; kt < nkt; kt++) {
        const float* kbase = Kg + base + (size_t)(kt * 32) * CC;
        const float* vbase = Vg + base + (size_t)(kt * 32) * CC;
        #pragma unroll
        for (int i = 0; i < 8; i++) {
            int p = i * 64 + tid;
            int r = p >> 4, c = p & 15;
            ((float4*)&Ks[r][0])[c] = ((const float4*)(kbase + (size_t)r * CC))[c];
            ((float4*)&Vs[r][0])[c] = ((const float4*)(vbase + (size_t)r * CC))[c];
        }
        __syncthreads();

        int jhi = qrow - kt * 32 + 1;
        if (jhi > 32) jhi = 32;
        if (jhi > 0) {
            float tmax = -INFINITY;
            #pragma unroll 2
            for (int j = 0; j < jhi; j++) {
                float4 a = make_float4(0.f, 0.f, 0.f, 0.f);
                #pragma unroll
                for (int i = 0; i < 16; i++) {
                    float4 kv = ((const float4*)&Ks[j][0])[i];
                    a.x = fmaf(q4[i].x, kv.x, a.x);
                    a.y = fmaf(q4[i].y, kv.y, a.y);
                    a.z = fmaf(q4[i].z, kv.z, a.z);
                    a.w = fmaf(q4[i].w, kv.w, a.w);
                }
                float sj = ((a.x + a.y) + (a.z + a.w)) * 0.125f; // 1/sqrt(64)
                Ss[j][tid] = sj;
                tmax = fmaxf(tmax, sj);
            }
            float mnew  = fmaxf(m, tmax);
            float alpha = __expf(m - mnew);
            l *= alpha;
            #pragma unroll
            for (int i = 0; i < 16; i++) {
                o4[i].x *= alpha; o4[i].y *= alpha;
                o4[i].z *= alpha; o4[i].w *= alpha;
            }
            #pragma unroll 2
            for (int j = 0; j < jhi; j++) {
                float p = __expf(Ss[j][tid] - mnew);
                l += p;
                #pragma unroll
                for (int i = 0; i < 16; i++) {
                    float4 vv = ((const float4*)&Vs[j][0])[i];
                    o4[i].x = fmaf(p, vv.x, o4[i].x);
                    o4[i].y = fmaf(p, vv.y, o4[i].y);
                    o4[i].z = fmaf(p, vv.z, o4[i].z);
                    o4[i].w = fmaf(p, vv.w, o4[i].w);
                }
            }
            m = mnew;
        }
        __syncthreads();
    }

    const float inv = 1.f / l;
    float4* op = (float4*)(O + base + (size_t)qrow * CC);
    #pragma unroll
    for (int i = 0; i < 16; i++)
        op[i] = make_float4(o4[i].x * inv, o4[i].y * inv,
                            o4[i].z * inv, o4[i].w * inv);
}

// ------------------------------ launch --------------------------------------
extern "C" void kernel_launch(void* const* d_in, const int* in_sizes, int n_in,
                              void* d_out, int out_size)
{
    (void)in_sizes; (void)n_in; (void)out_size;
    const float* x    = (const float*)d_in[0];
    // d_in[1] = mask (int32 tril) — causality is hard-coded in flash_kernel
    const float* ln1w = (const float*)d_in[2];
    const float* ln1b = (const float*)d_in[3];
    const float* ln2w = (const float*)d_in[4];
    const float* ln2b = (const float*)d_in[5];
    const float* wq   = (const float*)d_in[6];
    const float* bq   = (const float*)d_in[7];
    const float* wk   = (const float*)d_in[8];
    const float* bk   = (const float*)d_in[9];
    const float* wv   = (const float*)d_in[10];
    const float* bv   = (const float*)d_in[11];
    const float* wo   = (const float*)d_in[12];
    const float* bo   = (const float*)d_in[13];
    const float* w1   = (const float*)d_in[14];
    const float* b1   = (const float*)d_in[15];
    const float* w2   = (const float*)d_in[16];
    const float* b2   = (const float*)d_in[17];
    float* out = (float*)d_out;

    float *h, *q, *k, *v, *ctx, *x2, *ff;
    cudaGetSymbolAddress((void**)&h,   g_h);
    cudaGetSymbolAddress((void**)&q,   g_q);
    cudaGetSymbolAddress((void**)&k,   g_k);
    cudaGetSymbolAddress((void**)&v,   g_v);
    cudaGetSymbolAddress((void**)&ctx, g_ctx);
    cudaGetSymbolAddress((void**)&x2,  g_x2);
    cudaGetSymbolAddress((void**)&ff,  g_ff);

    const dim3 gC (CC  / 128, NROWS / 128);   // N=1024 GEMMs
    const dim3 gF (FFN / 128, NROWS / 128);   // N=4096 GEMM

    // 1. h = LN1(x)
    ln_kernel<<<NROWS, 256>>>(x, ln1w, ln1b, h);
    // 2. q,k,v = h@W + b
    sgemm_kernel<0><<<gC, 256>>>(h, wq, bq, nullptr, q, NROWS, CC, CC);
    sgemm_kernel<0><<<gC, 256>>>(h, wk, bk, nullptr, k, NROWS, CC, CC);
    sgemm_kernel<0><<<gC, 256>>>(h, wv, bv, nullptr, v, NROWS, CC, CC);
    // 3. ctx = causal-softmax(qk^T/8) v
    flash_kernel<<<dim3(TT / 64, BB * HHD), 64>>>(q, k, v, ctx);
    // 4. x2 = x + ctx@wo + bo
    sgemm_kernel<1><<<gC, 256>>>(ctx, wo, bo, x, x2, NROWS, CC, CC);
    // 5. h = LN2(x2)
    ln_kernel<<<NROWS, 256>>>(x2, ln2w, ln2b, h);
    // 6. ff = gelu(h@w1 + b1)
    sgemm_kernel<2><<<gF, 256>>>(h, w1, b1, nullptr, ff, NROWS, FFN, CC);
    // 7. out = x2 + ff@w2 + b2
    sgemm_kernel<1><<<gC, 256>>>(ff, w2, b2, x2, out, NROWS, CC, FFN);
}

// round 8
// speedup vs baseline: 1.9334x; 1.9334x over previous
#include <cuda_runtime.h>
#include <cuda_bf16.h>
#include <math.h>
#include <stdint.h>

// Problem constants
#define BB   8
#define TT   1024
#define CC   1024
#define HHD  16
#define DD   64
#define NROWS (BB*TT)      // 8192
#define FFN   (4*CC)       // 4096
#define EPS   1e-5f

// -------------------- scratch (static device memory; no allocs) ------------
__device__ float g_h  [(size_t)NROWS*CC];
__device__ float g_q  [(size_t)NROWS*CC];
__device__ float g_k  [(size_t)NROWS*CC];
__device__ float g_v  [(size_t)NROWS*CC];
__device__ float g_ctx[(size_t)NROWS*CC];
__device__ float g_x2 [(size_t)NROWS*CC];
__device__ float g_ff [(size_t)NROWS*FFN];
// transposed weights [N][K], K-major
__device__ float g_wqT[(size_t)CC*CC];
__device__ float g_wkT[(size_t)CC*CC];
__device__ float g_wvT[(size_t)CC*CC];
__device__ float g_woT[(size_t)CC*CC];
__device__ float g_w1T[(size_t)FFN*CC];
__device__ float g_w2T[(size_t)CC*FFN];

// ---------------------------- helpers ---------------------------------------
__device__ __forceinline__ uint32_t smem_to_u32(const void* p) {
    uint32_t a;
    asm("{ .reg .u64 t; cvta.to.shared.u64 t, %1; cvt.u32.u64 %0, t; }"
        : "=r"(a) : "l"(p));
    return a;
}

__device__ __forceinline__ void ldsm_x4(uint32_t* r, uint32_t addr) {
    asm volatile("ldmatrix.sync.aligned.m8n8.x4.shared.b16 {%0,%1,%2,%3}, [%4];"
                 : "=r"(r[0]), "=r"(r[1]), "=r"(r[2]), "=r"(r[3]) : "r"(addr));
}

__device__ __forceinline__ void mma_bf16(float* c, const uint32_t* a,
                                         const uint32_t* b) {
    asm volatile(
        "mma.sync.aligned.m16n8k16.row.col.f32.bf16.bf16.f32 "
        "{%0,%1,%2,%3}, {%4,%5,%6,%7}, {%8,%9}, {%0,%1,%2,%3};"
        : "+f"(c[0]), "+f"(c[1]), "+f"(c[2]), "+f"(c[3])
        : "r"(a[0]), "r"(a[1]), "r"(a[2]), "r"(a[3]), "r"(b[0]), "r"(b[1]));
}

__device__ __forceinline__ float gelu_exact(float v) {
    return 0.5f * v * (1.0f + erff(v * 0.70710678118654752f));
}

// --------------------------- weight transpose -------------------------------
__global__ __launch_bounds__(256) void transpose_kernel(
    const float* __restrict__ W, float* __restrict__ WT, int K, int N)
{
    __shared__ float t[32][33];
    const int n0 = blockIdx.x * 32, k0 = blockIdx.y * 32;
    const int tx = threadIdx.x, ty = threadIdx.y;
    #pragma unroll
    for (int i = 0; i < 32; i += 8)
        t[ty + i][tx] = W[(size_t)(k0 + ty + i) * N + n0 + tx];
    __syncthreads();
    #pragma unroll
    for (int i = 0; i < 32; i += 8)
        WT[(size_t)(n0 + ty + i) * K + k0 + tx] = t[tx][ty + i];
}

// ---------------------------- LayerNorm ------------------------------------
__global__ __launch_bounds__(256) void ln_kernel(
    const float* __restrict__ x, const float* __restrict__ w,
    const float* __restrict__ b, float* __restrict__ out)
{
    const int row = blockIdx.x;
    const int tid = threadIdx.x;
    const float4* xr = (const float4*)(x + (size_t)row * CC);
    float4 v = xr[tid];
    float s  = v.x + v.y + v.z + v.w;
    float ss = v.x*v.x + v.y*v.y + v.z*v.z + v.w*v.w;

    __shared__ float red0[8], red1[8];
    #pragma unroll
    for (int o = 16; o > 0; o >>= 1) {
        s  += __shfl_down_sync(0xffffffffu, s,  o);
        ss += __shfl_down_sync(0xffffffffu, ss, o);
    }
    const int wid = tid >> 5, lid = tid & 31;
    if (lid == 0) { red0[wid] = s; red1[wid] = ss; }
    __syncthreads();
    if (tid == 0) {
        float S = 0.f, SS = 0.f;
        #pragma unroll
        for (int i = 0; i < 8; i++) { S += red0[i]; SS += red1[i]; }
        float mu  = S * (1.f / CC);
        float var = SS * (1.f / CC) - mu * mu;
        red0[0] = mu;
        red1[0] = rsqrtf(var + EPS);
    }
    __syncthreads();
    const float mu = red0[0], rstd = red1[0];
    float4 wv = ((const float4*)w)[tid];
    float4 bv = ((const float4*)b)[tid];
    float4 o4;
    o4.x = (v.x - mu) * rstd * wv.x + bv.x;
    o4.y = (v.y - mu) * rstd * wv.y + bv.y;
    o4.z = (v.z - mu) * rstd * wv.z + bv.z;
    o4.w = (v.w - mu) * rstd * wv.w + bv.w;
    ((float4*)(out + (size_t)row * CC))[tid] = o4;
}

// --------------------- bf16x3 mma.sync GEMM ---------------------------------
// C[M,N] = epilogue(A[M,K] @ BT[N,K]^T + bias, res)
// EPI 0: +bias   EPI 1: +bias+res   EPI 2: gelu(+bias)
// CTA 128x128x32, 256 thr, warps 4(m) x 2(n), each warp 32x64.
// SMEM: per stage, 4 tiles (Ah, Al, Bh, Bl) of 128 rows x 32 bf16, 80B pitch.

#define PITCH      80
#define TILE_B     (128 * PITCH)               // 10240
#define SOFF(st,w) (((st)*4 + (w)) * TILE_B)
#define GEMM_SMEM  (8 * TILE_B)                // 81920

__device__ __forceinline__ uint2 pack_split(float4 v, uint2& lo_out) {
    __nv_bfloat162 h01, h23, l01, l23;
    h01.x = __float2bfloat16_rn(v.x);
    h01.y = __float2bfloat16_rn(v.y);
    h23.x = __float2bfloat16_rn(v.z);
    h23.y = __float2bfloat16_rn(v.w);
    l01.x = __float2bfloat16_rn(v.x - __bfloat162float(h01.x));
    l01.y = __float2bfloat16_rn(v.y - __bfloat162float(h01.y));
    l23.x = __float2bfloat16_rn(v.z - __bfloat162float(h23.x));
    l23.y = __float2bfloat16_rn(v.w - __bfloat162float(h23.y));
    uint2 hi;
    hi.x = *(uint32_t*)&h01;  hi.y = *(uint32_t*)&h23;
    lo_out.x = *(uint32_t*)&l01;  lo_out.y = *(uint32_t*)&l23;
    return hi;
}

template<int EPI>
__global__ __launch_bounds__(256, 1) void gemm_bf16x3(
    const float* __restrict__ A, const float* __restrict__ BT,
    const float* __restrict__ bias, const float* __restrict__ res,
    float* __restrict__ C, int M, int N, int K)
{
    extern __shared__ char smemc[];
    const uint32_t sb = smem_to_u32(smemc);

    const int tid    = threadIdx.x;
    const int wid    = tid >> 5, lane = tid & 31;
    const int warp_m = wid & 3;          // 4 warps along M
    const int warp_n = wid >> 2;         // 2 warps along N
    const int brow   = blockIdx.y * 128;
    const int bcol   = blockIdx.x * 128;

    // global load mapping: thread covers rows r0+{0,32,64,96}, float4 col c4
    const int r0 = tid >> 3;             // 0..31
    const int c4 = tid & 7;              // 0..7
    const float* Ag = A  + (size_t)brow * K;
    const float* Bg = BT + (size_t)bcol * K;
    const uint32_t sts_off = (uint32_t)(r0 * PITCH + c4 * 8);

    float acc[64];
    #pragma unroll
    for (int i = 0; i < 64; i++) acc[i] = 0.f;

    const int NKB = K >> 5;
    float4 av[4], bv[4];

    // prologue: load chunk 0
    #pragma unroll
    for (int i = 0; i < 4; i++) {
        const int row = r0 + i * 32;
        av[i] = *(const float4*)(Ag + (size_t)row * K + c4 * 4);
        bv[i] = *(const float4*)(Bg + (size_t)row * K + c4 * 4);
    }
    #pragma unroll
    for (int i = 0; i < 4; i++) {
        const uint32_t so = sts_off + i * 32 * PITCH;
        uint2 lo, hi;
        hi = pack_split(av[i], lo);
        *(uint2*)(smemc + SOFF(0,0) + so) = hi;
        *(uint2*)(smemc + SOFF(0,1) + so) = lo;
        hi = pack_split(bv[i], lo);
        *(uint2*)(smemc + SOFF(0,2) + so) = hi;
        *(uint2*)(smemc + SOFF(0,3) + so) = lo;
    }
    __syncthreads();

    // ldmatrix per-lane offsets
    const int a_row = warp_m * 32 + (lane & 7) + ((lane >> 3) & 1) * 8;
    const int a_kc  = (lane >> 4);                    // chunk (k/8) within k16
    const uint32_t a_off = (uint32_t)(a_row * PITCH + a_kc * 16);
    const int b_row = warp_n * 64 + (lane & 7) + (lane >> 4) * 8;
    const int b_kc  = ((lane >> 3) & 1);
    const uint32_t b_off = (uint32_t)(b_row * PITCH + b_kc * 16);

    for (int kb = 0; kb < NKB; kb++) {
        const int cur = kb & 1;
        const uint32_t sAh = sb + SOFF(cur,0), sAl = sb + SOFF(cur,1);
        const uint32_t sBh = sb + SOFF(cur,2), sBl = sb + SOFF(cur,3);

        // issue next global loads early (hidden under MMA)
        if (kb + 1 < NKB) {
            const int ke = (kb + 1) << 5;
            #pragma unroll
            for (int i = 0; i < 4; i++) {
                const int row = r0 + i * 32;
                av[i] = *(const float4*)(Ag + (size_t)row * K + ke + c4 * 4);
                bv[i] = *(const float4*)(Bg + (size_t)row * K + ke + c4 * 4);
            }
        }

        #pragma unroll
        for (int k16 = 0; k16 < 2; k16++) {
            uint32_t ah[2][4], al[2][4];
            #pragma unroll
            for (int mt = 0; mt < 2; mt++) {
                const uint32_t off = a_off + mt * 16 * PITCH + k16 * 32;
                ldsm_x4(ah[mt], sAh + off);
                ldsm_x4(al[mt], sAl + off);
            }
            #pragma unroll
            for (int nt = 0; nt < 4; nt++) {
                uint32_t bh[4], bl[4];
                const uint32_t off = b_off + nt * 16 * PITCH + k16 * 32;
                ldsm_x4(bh, sBh + off);
                ldsm_x4(bl, sBl + off);
                #pragma unroll
                for (int mt = 0; mt < 2; mt++)
                    #pragma unroll
                    for (int t = 0; t < 2; t++)
                        mma_bf16(&acc[(mt*8 + nt*2 + t)*4], ah[mt], &bl[t*2]);
                #pragma unroll
                for (int mt = 0; mt < 2; mt++)
                    #pragma unroll
                    for (int t = 0; t < 2; t++)
                        mma_bf16(&acc[(mt*8 + nt*2 + t)*4], al[mt], &bh[t*2]);
                #pragma unroll
                for (int mt = 0; mt < 2; mt++)
                    #pragma unroll
                    for (int t = 0; t < 2; t++)
                        mma_bf16(&acc[(mt*8 + nt*2 + t)*4], ah[mt], &bh[t*2]);
            }
        }

        // write next chunk into the other buffer
        if (kb + 1 < NKB) {
            const int nb = cur ^ 1;
            #pragma unroll
            for (int i = 0; i < 4; i++) {
                const uint32_t so = sts_off + i * 32 * PITCH;
                uint2 lo, hi;
                hi = pack_split(av[i], lo);
                *(uint2*)(smemc + SOFF(nb,0) + so) = hi;
                *(uint2*)(smemc + SOFF(nb,1) + so) = lo;
                hi = pack_split(bv[i], lo);
                *(uint2*)(smemc + SOFF(nb,2) + so) = hi;
                *(uint2*)(smemc + SOFF(nb,3) + so) = lo;
            }
        }
        __syncthreads();
    }

    // ---------------- epilogue ----------------
    const int erow = brow + warp_m * 32 + (lane >> 2);
    const int ecol = bcol + warp_n * 64 + (lane & 3) * 2;
    #pragma unroll
    for (int mt = 0; mt < 2; mt++) {
        #pragma unroll
        for (int j = 0; j < 8; j++) {
            const float* c = &acc[(mt*8 + j)*4];
            const int grow = erow + mt * 16;
            const int gcol = ecol + j * 8;
            float2 bvv = *(const float2*)(bias + gcol);
            float2 o0, o1;
            o0.x = c[0] + bvv.x;  o0.y = c[1] + bvv.y;
            o1.x = c[2] + bvv.x;  o1.y = c[3] + bvv.y;
            if (EPI == 1) {
                float2 r0v = *(const float2*)(res + (size_t)grow * N + gcol);
                float2 r1v = *(const float2*)(res + (size_t)(grow+8) * N + gcol);
                o0.x += r0v.x; o0.y += r0v.y;
                o1.x += r1v.x; o1.y += r1v.y;
            }
            if (EPI == 2) {
                o0.x = gelu_exact(o0.x); o0.y = gelu_exact(o0.y);
                o1.x = gelu_exact(o1.x); o1.y = gelu_exact(o1.y);
            }
            *(float2*)(C + (size_t)grow * N + gcol)     = o0;
            *(float2*)(C + (size_t)(grow+8) * N + gcol) = o1;
        }
    }
}

// --------------------------- Flash attention --------------------------------
__global__ __launch_bounds__(64) void flash_kernel(
    const float* __restrict__ Q, const float* __restrict__ Kg,
    const float* __restrict__ Vg, float* __restrict__ O)
{
    __shared__ float Ks[32][64];
    __shared__ float Vs[32][64];
    __shared__ float Ss[32][64];

    const int qt  = blockIdx.x;
    const int bh  = blockIdx.y;
    const int b   = bh >> 4;
    const int hh  = bh & 15;
    const int tid = threadIdx.x;
    const int qrow = qt * 64 + tid;

    const size_t base = ((size_t)b * TT) * CC + (size_t)hh * DD;

    float4 q4[16], o4[16];
    {
        const float4* qp = (const float4*)(Q + base + (size_t)qrow * CC);
        #pragma unroll
        for (int i = 0; i < 16; i++) {
            q4[i] = qp[i];
            o4[i] = make_float4(0.f, 0.f, 0.f, 0.f);
        }
    }
    float m = -INFINITY, l = 0.f;

    const int nkt = 2 * qt + 2;
    for (int kt = 0; kt < nkt; kt++) {
        const float* kbase = Kg + base + (size_t)(kt * 32) * CC;
        const float* vbase = Vg + base + (size_t)(kt * 32) * CC;
        #pragma unroll
        for (int i = 0; i < 8; i++) {
            int p = i * 64 + tid;
            int r = p >> 4, c = p & 15;
            ((float4*)&Ks[r][0])[c] = ((const float4*)(kbase + (size_t)r * CC))[c];
            ((float4*)&Vs[r][0])[c] = ((const float4*)(vbase + (size_t)r * CC))[c];
        }
        __syncthreads();

        int jhi = qrow - kt * 32 + 1;
        if (jhi > 32) jhi = 32;
        if (jhi > 0) {
            float tmax = -INFINITY;
            #pragma unroll 2
            for (int j = 0; j < jhi; j++) {
                float4 a = make_float4(0.f, 0.f, 0.f, 0.f);
                #pragma unroll
                for (int i = 0; i < 16; i++) {
                    float4 kv = ((const float4*)&Ks[j][0])[i];
                    a.x = fmaf(q4[i].x, kv.x, a.x);
                    a.y = fmaf(q4[i].y, kv.y, a.y);
                    a.z = fmaf(q4[i].z, kv.z, a.z);
                    a.w = fmaf(q4[i].w, kv.w, a.w);
                }
                float sj = ((a.x + a.y) + (a.z + a.w)) * 0.125f;
                Ss[j][tid] = sj;
                tmax = fmaxf(tmax, sj);
            }
            float mnew  = fmaxf(m, tmax);
            float alpha = __expf(m - mnew);
            l *= alpha;
            #pragma unroll
            for (int i = 0; i < 16; i++) {
                o4[i].x *= alpha; o4[i].y *= alpha;
                o4[i].z *= alpha; o4[i].w *= alpha;
            }
            #pragma unroll 2
            for (int j = 0; j < jhi; j++) {
                float p = __expf(Ss[j][tid] - mnew);
                l += p;
                #pragma unroll
                for (int i = 0; i < 16; i++) {
                    float4 vv = ((const float4*)&Vs[j][0])[i];
                    o4[i].x = fmaf(p, vv.x, o4[i].x);
                    o4[i].y = fmaf(p, vv.y, o4[i].y);
                    o4[i].z = fmaf(p, vv.z, o4[i].z);
                    o4[i].w = fmaf(p, vv.w, o4[i].w);
                }
            }
            m = mnew;
        }
        __syncthreads();
    }

    const float inv = 1.f / l;
    float4* op = (float4*)(O + base + (size_t)qrow * CC);
    #pragma unroll
    for (int i = 0; i < 16; i++)
        op[i] = make_float4(o4[i].x * inv, o4[i].y * inv,
                            o4[i].z * inv, o4[i].w * inv);
}

// ------------------------------ launch --------------------------------------
extern "C" void kernel_launch(void* const* d_in, const int* in_sizes, int n_in,
                              void* d_out, int out_size)
{
    (void)in_sizes; (void)n_in; (void)out_size;
    const float* x    = (const float*)d_in[0];
    const float* ln1w = (const float*)d_in[2];
    const float* ln1b = (const float*)d_in[3];
    const float* ln2w = (const float*)d_in[4];
    const float* ln2b = (const float*)d_in[5];
    const float* wq   = (const float*)d_in[6];
    const float* bq   = (const float*)d_in[7];
    const float* wk   = (const float*)d_in[8];
    const float* bk   = (const float*)d_in[9];
    const float* wv   = (const float*)d_in[10];
    const float* bv   = (const float*)d_in[11];
    const float* wo   = (const float*)d_in[12];
    const float* bo   = (const float*)d_in[13];
    const float* w1   = (const float*)d_in[14];
    const float* b1   = (const float*)d_in[15];
    const float* w2   = (const float*)d_in[16];
    const float* b2   = (const float*)d_in[17];
    float* out = (float*)d_out;

    float *h, *q, *k, *v, *ctx, *x2, *ff;
    float *wqT, *wkT, *wvT, *woT, *w1T, *w2T;
    cudaGetSymbolAddress((void**)&h,   g_h);
    cudaGetSymbolAddress((void**)&q,   g_q);
    cudaGetSymbolAddress((void**)&k,   g_k);
    cudaGetSymbolAddress((void**)&v,   g_v);
    cudaGetSymbolAddress((void**)&ctx, g_ctx);
    cudaGetSymbolAddress((void**)&x2,  g_x2);
    cudaGetSymbolAddress((void**)&ff,  g_ff);
    cudaGetSymbolAddress((void**)&wqT, g_wqT);
    cudaGetSymbolAddress((void**)&wkT, g_wkT);
    cudaGetSymbolAddress((void**)&wvT, g_wvT);
    cudaGetSymbolAddress((void**)&woT, g_woT);
    cudaGetSymbolAddress((void**)&w1T, g_w1T);
    cudaGetSymbolAddress((void**)&w2T, g_w2T);

    cudaFuncSetAttribute(gemm_bf16x3<0>, cudaFuncAttributeMaxDynamicSharedMemorySize, GEMM_SMEM);
    cudaFuncSetAttribute(gemm_bf16x3<1>, cudaFuncAttributeMaxDynamicSharedMemorySize, GEMM_SMEM);
    cudaFuncSetAttribute(gemm_bf16x3<2>, cudaFuncAttributeMaxDynamicSharedMemorySize, GEMM_SMEM);

    const dim3 tB(32, 8);
    transpose_kernel<<<dim3(CC/32,  CC/32),  tB>>>(wq, wqT, CC,  CC);
    transpose_kernel<<<dim3(CC/32,  CC/32),  tB>>>(wk, wkT, CC,  CC);
    transpose_kernel<<<dim3(CC/32,  CC/32),  tB>>>(wv, wvT, CC,  CC);
    transpose_kernel<<<dim3(CC/32,  CC/32),  tB>>>(wo, woT, CC,  CC);
    transpose_kernel<<<dim3(FFN/32, CC/32),  tB>>>(w1, w1T, CC,  FFN);
    transpose_kernel<<<dim3(CC/32,  FFN/32), tB>>>(w2, w2T, FFN, CC);

    const dim3 gC(CC  / 128, NROWS / 128);
    const dim3 gF(FFN / 128, NROWS / 128);

    // 1. h = LN1(x)
    ln_kernel<<<NROWS, 256>>>(x, ln1w, ln1b, h);
    // 2. q,k,v = h@W + b
    gemm_bf16x3<0><<<gC, 256, GEMM_SMEM>>>(h, wqT, bq, nullptr, q, NROWS, CC, CC);
    gemm_bf16x3<0><<<gC, 256, GEMM_SMEM>>>(h, wkT, bk, nullptr, k, NROWS, CC, CC);
    gemm_bf16x3<0><<<gC, 256, GEMM_SMEM>>>(h, wvT, bv, nullptr, v, NROWS, CC, CC);
    // 3. ctx = causal-softmax(qk^T/8) v
    flash_kernel<<<dim3(TT / 64, BB * HHD), 64>>>(q, k, v, ctx);
    // 4. x2 = x + ctx@wo + bo
    gemm_bf16x3<1><<<gC, 256, GEMM_SMEM>>>(ctx, woT, bo, x, x2, NROWS, CC, CC);
    // 5. h = LN2(x2)
    ln_kernel<<<NROWS, 256>>>(x2, ln2w, ln2b, h);
    // 6. ff = gelu(h@w1 + b1)
    gemm_bf16x3<2><<<gF, 256, GEMM_SMEM>>>(h, w1T, b1, nullptr, ff, NROWS, FFN, CC);
    // 7. out = x2 + ff@w2 + b2
    gemm_bf16x3<1><<<gC, 256, GEMM_SMEM>>>(ff, w2T, b2, x2, out, NROWS, CC, FFN);
}